// round 6
// baseline (speedup 1.0000x reference)
#include <cuda_runtime.h>
#include <cstdint>

// out[2048,122880] = tile(x1[2048,4096] @ x2[4096,4096], 30x), fp32, TF32 mma.sync.
// R6: occupancy attack. 128x128x32 tiles, 8 warps/CTA (64x32 warp tile),
// 2 CTAs/SM => 16 warps/SM. 3-stage cp.async, fragment-order operands.
#define MDIM 2048
#define NDIM 4096
#define KDIM 4096
#define NREP 30
#define OUTN (NDIM * NREP)

#define BM 128
#define BN 128
#define BK 32
#define NKT (KDIM / BK)          // 128
#define STAGES 3
#define STAGE_BYTES 32768        // 16KB A frags + 16KB B frags
#define SMEM_TOTAL (STAGES * STAGE_BYTES)   // 96KB -> 2 CTAs/SM

__device__ float g_Af[(size_t)MDIM * KDIM];
__device__ float g_Bf[(size_t)NDIM * KDIM];

__device__ __forceinline__ uint32_t f2tf32(float x) {
    uint32_t y;
    asm("cvt.rna.tf32.f32 %0, %1;" : "=r"(y) : "f"(x));
    return y;
}
__device__ __forceinline__ float rtf(float x) { return __uint_as_float(f2tf32(x)); }

__device__ __forceinline__ uint32_t smem_u32(const void* p) {
    uint32_t a;
    asm("{ .reg .u64 t; cvta.to.shared.u64 t, %1; cvt.u32.u64 %0, t; }" : "=r"(a) : "l"(p));
    return a;
}
__device__ __forceinline__ void cp_async16(uint32_t dst, const void* src) {
    asm volatile("cp.async.cg.shared.global [%0], [%1], 16;" :: "r"(dst), "l"(src) : "memory");
}
#define CP_COMMIT() asm volatile("cp.async.commit_group;" ::: "memory")
#define CP_WAIT1()  asm volatile("cp.async.wait_group 1;" ::: "memory")

__device__ __forceinline__ void mma_tf32(float c[4], uint32_t a0, uint32_t a1,
                                         uint32_t a2, uint32_t a3,
                                         uint32_t b0, uint32_t b1) {
    asm volatile(
        "mma.sync.aligned.m16n8k8.row.col.f32.tf32.tf32.f32 "
        "{%0,%1,%2,%3},{%4,%5,%6,%7},{%8,%9},{%0,%1,%2,%3};"
        : "+f"(c[0]), "+f"(c[1]), "+f"(c[2]), "+f"(c[3])
        : "r"(a0), "r"(a1), "r"(a2), "r"(a3), "r"(b0), "r"(b1));
}

// ---------------- fused prepass: blocks [0,1024) do A, [1024,3072) do B ----------------
__global__ __launch_bounds__(256)
void prep_kernel(const float* __restrict__ A, const float* __restrict__ B) {
    __shared__ float sbuf[128 * 68];       // A view 16x516, B view 128x68
    const int tid = threadIdx.x, lane = tid & 31, warp = tid >> 5;
    const int r = lane >> 2, cq = lane & 3;

    if (blockIdx.x < 1024) {
        const int bx = blockIdx.x & 7;      // K/512
        const int m16 = blockIdx.x >> 3;    // M/16
        #pragma unroll
        for (int i = 0; i < 8; i++) {
            const int idx = i * 256 + tid;
            const int rr = idx >> 7, c4 = idx & 127;
            float4 v = *(const float4*)&A[(size_t)(m16 * 16 + rr) * KDIM + bx * 512 + c4 * 4];
            v.x = rtf(v.x); v.y = rtf(v.y); v.z = rtf(v.z); v.w = rtf(v.w);
            *(float4*)&sbuf[rr * 516 + c4 * 4] = v;
        }
        __syncthreads();
        #pragma unroll
        for (int t = 0; t < 8; t++) {
            const int k8l = warp * 8 + t;
            float4 w;
            w.x = sbuf[r * 516 + k8l * 8 + cq];
            w.y = sbuf[(r + 8) * 516 + k8l * 8 + cq];
            w.z = sbuf[r * 516 + k8l * 8 + cq + 4];
            w.w = sbuf[(r + 8) * 516 + k8l * 8 + cq + 4];
            const size_t o = ((size_t)m16 * 512 + bx * 64 + k8l) * 32 + lane;
            ((float4*)g_Af)[o] = w;
        }
    } else {
        const int id = blockIdx.x - 1024;
        const int bx = id & 31;             // K/128
        const int by = id >> 5;             // N/64
        #pragma unroll
        for (int i = 0; i < 8; i++) {
            const int idx = i * 256 + tid;
            const int kr = idx >> 4, c4 = idx & 15;
            float4 v = *(const float4*)&B[(size_t)(bx * 128 + kr) * NDIM + by * 64 + c4 * 4];
            v.x = rtf(v.x); v.y = rtf(v.y); v.z = rtf(v.z); v.w = rtf(v.w);
            *(float4*)&sbuf[kr * 68 + c4 * 4] = v;
        }
        __syncthreads();
        #pragma unroll
        for (int t = 0; t < 8; t++) {
            const int id2 = warp * 8 + t;
            const int n16l = id2 >> 4, k8l = id2 & 15;
            float4 w;
            w.x = sbuf[(k8l * 8 + cq) * 68 + n16l * 16 + r];
            w.y = sbuf[(k8l * 8 + cq + 4) * 68 + n16l * 16 + r];
            w.z = sbuf[(k8l * 8 + cq) * 68 + n16l * 16 + 8 + r];
            w.w = sbuf[(k8l * 8 + cq + 4) * 68 + n16l * 16 + 8 + r];
            const size_t o = ((size_t)(by * 4 + n16l) * 512 + bx * 16 + k8l) * 32 + lane;
            ((float4*)g_Bf)[o] = w;
        }
    }
}

// ---------------- GEMM: 128x128x32, 8 warps of 64x32, 2 CTAs/SM, 3-stage ----------------
__global__ __launch_bounds__(256, 2)
void Model_82454782148931_gemm(float* __restrict__ out) {
    extern __shared__ char smem[];
    const uint32_t sbase = smem_u32(smem);
    const int tid  = threadIdx.x;
    const int lane = tid & 31;
    const int warp = tid >> 5;
    const int wm   = warp & 1;              // 0..1 -> 64-row slab
    const int wn   = warp >> 1;             // 0..3 -> 32-col slab
    const int mi   = blockIdx.x & 15;       // m fastest: concurrent CTAs share B in L2
    const int ni   = blockIdx.x >> 4;       // 0..31
    const int bm16 = mi * 8;
    const int bn16 = ni * 8;

    const float4* Af4 = (const float4*)g_Af;
    const float4* Bf4 = (const float4*)g_Bf;

    float c[4][4][4];
    #pragma unroll
    for (int mt = 0; mt < 4; mt++)
        #pragma unroll
        for (int nt = 0; nt < 4; nt++)
            #pragma unroll
            for (int i = 0; i < 4; i++) c[mt][nt][i] = 0.0f;

    auto load_stage = [&](int s, int kt) {
        const uint32_t ab = sbase + s * STAGE_BYTES;
        #pragma unroll
        for (int i = 0; i < 4; i++) {       // A: 1024 float4 (16KB)
            const int idx = i * 256 + tid;
            const int m16l = idx >> 7;
            const int k8l  = (idx >> 5) & 3;
            const int ln   = idx & 31;
            cp_async16(ab + idx * 16,
                       Af4 + ((size_t)(bm16 + m16l) * 512 + kt * 4 + k8l) * 32 + ln);
        }
        #pragma unroll
        for (int i = 0; i < 4; i++) {       // B: 1024 float4 (16KB)
            const int idx = i * 256 + tid;
            const int n16l = idx >> 7;
            const int k8l  = (idx >> 5) & 3;
            const int ln   = idx & 31;
            cp_async16(ab + 16384 + idx * 16,
                       Bf4 + ((size_t)(bn16 + n16l) * 512 + kt * 4 + k8l) * 32 + ln);
        }
    };

    load_stage(0, 0); CP_COMMIT();
    load_stage(1, 1); CP_COMMIT();

    #pragma unroll 1
    for (int kt = 0; kt < NKT; kt++) {
        const int s = kt % STAGES;
        CP_WAIT1();                         // stage kt landed (kt+1 in flight)
        __syncthreads();
        if (kt + 2 < NKT) load_stage((kt + 2) % STAGES, kt + 2);
        CP_COMMIT();

        // A frags for warp's 64 rows: m16l = wm*4..wm*4+3; B: n16l = wn*2..wn*2+1
        const char* ap = smem + s * STAGE_BYTES + (size_t)(wm * 4) * 4 * 512 + lane * 16;
        const char* bp = smem + s * STAGE_BYTES + 16384 + (size_t)(wn * 2) * 4 * 512 + lane * 16;
        #pragma unroll
        for (int ks = 0; ks < 4; ks++) {
            uint4 af[4], bf[2];
            #pragma unroll
            for (int mt = 0; mt < 4; mt++)
                af[mt] = *(const uint4*)(ap + (mt * 4 + ks) * 512);
            #pragma unroll
            for (int j = 0; j < 2; j++)
                bf[j] = *(const uint4*)(bp + (j * 4 + ks) * 512);
            #pragma unroll
            for (int mt = 0; mt < 4; mt++)
                #pragma unroll
                for (int j = 0; j < 2; j++) {
                    mma_tf32(c[mt][2 * j],     af[mt].x, af[mt].y, af[mt].z, af[mt].w,
                             bf[j].x, bf[j].y);
                    mma_tf32(c[mt][2 * j + 1], af[mt].x, af[mt].y, af[mt].z, af[mt].w,
                             bf[j].z, bf[j].w);
                }
        }
    }

    // ---- epilogue: 30 replicas straight from registers, full-sector float2 __stcs ----
    const int bm0 = mi * BM;
    const int bn0 = ni * BN;
    #pragma unroll
    for (int mt = 0; mt < 4; mt++) {
        const int row0 = bm0 + wm * 64 + mt * 16 + (lane >> 2);
        #pragma unroll
        for (int nt = 0; nt < 4; nt++) {
            const int col = bn0 + wn * 32 + nt * 8 + (lane & 3) * 2;
            const float2 v01 = make_float2(c[mt][nt][0], c[mt][nt][1]);
            const float2 v23 = make_float2(c[mt][nt][2], c[mt][nt][3]);
            float* p0 = out + (size_t)row0 * OUTN + col;
            float* p1 = p0 + (size_t)8 * OUTN;
            #pragma unroll
            for (int rep = 0; rep < NREP; rep++) {
                __stcs((float2*)(p0 + (size_t)rep * NDIM), v01);
                __stcs((float2*)(p1 + (size_t)rep * NDIM), v23);
            }
        }
    }
}

extern "C" void kernel_launch(void* const* d_in, const int* in_sizes, int n_in,
                              void* d_out, int out_size) {
    const float* x1 = (const float*)d_in[0];
    const float* x2 = (const float*)d_in[1];
    float* out = (float*)d_out;

    prep_kernel<<<3072, 256>>>(x1, x2);

    cudaFuncSetAttribute(Model_82454782148931_gemm,
                         cudaFuncAttributeMaxDynamicSharedMemorySize, SMEM_TOTAL);
    Model_82454782148931_gemm<<<512, 256, SMEM_TOTAL>>>(out);   // m-fastest, 2 CTAs/SM
}

// round 7
// speedup vs baseline: 1.2259x; 1.2259x over previous
#include <cuda_runtime.h>
#include <cstdint>

// out[2048,122880] = tile(x1[2048,4096] @ x2[4096,4096], 30x), fp32, TF32 mma.sync.
// R7: R3's winning config (128x128x32, 4 warps 64x64, 2 CTA/SM, 3-stage) +
// fused prep + cp.async issue interleaved into the ks pipeline + shuffle STG.128
// epilogue. Everything that competes with HMMA issue slots is minimized.
#define MDIM 2048
#define NDIM 4096
#define KDIM 4096
#define NREP 30
#define OUTN (NDIM * NREP)

#define BM 128
#define BN 128
#define BK 32
#define NKT (KDIM / BK)          // 128
#define STAGES 3
#define STAGE_BYTES 32768        // 16KB A frags + 16KB B frags
#define SMEM_TOTAL (STAGES * STAGE_BYTES)   // 96KB -> 2 CTAs/SM

__device__ float g_Af[(size_t)MDIM * KDIM];
__device__ float g_Bf[(size_t)NDIM * KDIM];

__device__ __forceinline__ uint32_t f2tf32(float x) {
    uint32_t y;
    asm("cvt.rna.tf32.f32 %0, %1;" : "=r"(y) : "f"(x));
    return y;
}
__device__ __forceinline__ float rtf(float x) { return __uint_as_float(f2tf32(x)); }

__device__ __forceinline__ uint32_t smem_u32(const void* p) {
    uint32_t a;
    asm("{ .reg .u64 t; cvta.to.shared.u64 t, %1; cvt.u32.u64 %0, t; }" : "=r"(a) : "l"(p));
    return a;
}
__device__ __forceinline__ void cp_async16(uint32_t dst, const void* src) {
    asm volatile("cp.async.cg.shared.global [%0], [%1], 16;" :: "r"(dst), "l"(src) : "memory");
}
#define CP_COMMIT() asm volatile("cp.async.commit_group;" ::: "memory")
#define CP_WAIT1()  asm volatile("cp.async.wait_group 1;" ::: "memory")

__device__ __forceinline__ void mma_tf32(float c[4], uint32_t a0, uint32_t a1,
                                         uint32_t a2, uint32_t a3,
                                         uint32_t b0, uint32_t b1) {
    asm volatile(
        "mma.sync.aligned.m16n8k8.row.col.f32.tf32.tf32.f32 "
        "{%0,%1,%2,%3},{%4,%5,%6,%7},{%8,%9},{%0,%1,%2,%3};"
        : "+f"(c[0]), "+f"(c[1]), "+f"(c[2]), "+f"(c[3])
        : "r"(a0), "r"(a1), "r"(a2), "r"(a3), "r"(b0), "r"(b1));
}

// ---------------- fused prepass: blocks [0,1024) do A, [1024,3072) do B ----------------
__global__ __launch_bounds__(256)
void prep_kernel(const float* __restrict__ A, const float* __restrict__ B) {
    __shared__ float sbuf[128 * 68];       // A view 16x516, B view 128x68
    const int tid = threadIdx.x, lane = tid & 31, warp = tid >> 5;
    const int r = lane >> 2, cq = lane & 3;

    if (blockIdx.x < 1024) {
        const int bx = blockIdx.x & 7;      // K/512
        const int m16 = blockIdx.x >> 3;    // M/16
        #pragma unroll
        for (int i = 0; i < 8; i++) {
            const int idx = i * 256 + tid;
            const int rr = idx >> 7, c4 = idx & 127;
            float4 v = *(const float4*)&A[(size_t)(m16 * 16 + rr) * KDIM + bx * 512 + c4 * 4];
            v.x = rtf(v.x); v.y = rtf(v.y); v.z = rtf(v.z); v.w = rtf(v.w);
            *(float4*)&sbuf[rr * 516 + c4 * 4] = v;
        }
        __syncthreads();
        #pragma unroll
        for (int t = 0; t < 8; t++) {
            const int k8l = warp * 8 + t;
            float4 w;
            w.x = sbuf[r * 516 + k8l * 8 + cq];
            w.y = sbuf[(r + 8) * 516 + k8l * 8 + cq];
            w.z = sbuf[r * 516 + k8l * 8 + cq + 4];
            w.w = sbuf[(r + 8) * 516 + k8l * 8 + cq + 4];
            const size_t o = ((size_t)m16 * 512 + bx * 64 + k8l) * 32 + lane;
            ((float4*)g_Af)[o] = w;
        }
    } else {
        const int id = blockIdx.x - 1024;
        const int bx = id & 31;             // K/128
        const int by = id >> 5;             // N/64
        #pragma unroll
        for (int i = 0; i < 8; i++) {
            const int idx = i * 256 + tid;
            const int kr = idx >> 4, c4 = idx & 15;
            float4 v = *(const float4*)&B[(size_t)(bx * 128 + kr) * NDIM + by * 64 + c4 * 4];
            v.x = rtf(v.x); v.y = rtf(v.y); v.z = rtf(v.z); v.w = rtf(v.w);
            *(float4*)&sbuf[kr * 68 + c4 * 4] = v;
        }
        __syncthreads();
        #pragma unroll
        for (int t = 0; t < 8; t++) {
            const int id2 = warp * 8 + t;
            const int n16l = id2 >> 4, k8l = id2 & 15;
            float4 w;
            w.x = sbuf[(k8l * 8 + cq) * 68 + n16l * 16 + r];
            w.y = sbuf[(k8l * 8 + cq + 4) * 68 + n16l * 16 + r];
            w.z = sbuf[(k8l * 8 + cq) * 68 + n16l * 16 + 8 + r];
            w.w = sbuf[(k8l * 8 + cq + 4) * 68 + n16l * 16 + 8 + r];
            const size_t o = ((size_t)(by * 4 + n16l) * 512 + bx * 16 + k8l) * 32 + lane;
            ((float4*)g_Bf)[o] = w;
        }
    }
}

// ---------------- GEMM: 128x128x32, 4 warps of 64x64, 2 CTAs/SM, 3-stage ----------------
__global__ __launch_bounds__(128, 2)
void Model_82454782148931_gemm(float* __restrict__ out) {
    extern __shared__ char smem[];
    const uint32_t sbase = smem_u32(smem);
    const int tid  = threadIdx.x;
    const int lane = tid & 31;
    const int warp = tid >> 5;
    const int wm   = warp >> 1;             // 0..1 -> 64-row slab
    const int wn   = warp & 1;              // 0..1 -> 64-col slab
    const int bm16 = blockIdx.y * 8;
    const int bn16 = blockIdx.x * 8;

    const float4* Af4 = (const float4*)g_Af;
    const float4* Bf4 = (const float4*)g_Bf;

    float c[4][8][4];
    #pragma unroll
    for (int mt = 0; mt < 4; mt++)
        #pragma unroll
        for (int nt = 0; nt < 8; nt++)
            #pragma unroll
            for (int i = 0; i < 4; i++) c[mt][nt][i] = 0.0f;

    // per-thread cp.async source/dest (8 A-f4 + 8 B-f4 per thread per stage)
    auto load_A = [&](uint32_t ab, int kt) {
        #pragma unroll
        for (int i = 0; i < 8; i++) {
            const int idx = i * 128 + tid;  // 1024 float4
            const int m16l = idx >> 7;
            const int k8l  = (idx >> 5) & 3;
            const int ln   = idx & 31;
            cp_async16(ab + idx * 16,
                       Af4 + ((size_t)(bm16 + m16l) * 512 + kt * 4 + k8l) * 32 + ln);
        }
    };
    auto load_B = [&](uint32_t ab, int kt) {
        #pragma unroll
        for (int i = 0; i < 8; i++) {
            const int idx = i * 128 + tid;
            const int n16l = idx >> 7;
            const int k8l  = (idx >> 5) & 3;
            const int ln   = idx & 31;
            cp_async16(ab + 16384 + idx * 16,
                       Bf4 + ((size_t)(bn16 + n16l) * 512 + kt * 4 + k8l) * 32 + ln);
        }
    };

    load_A(sbase, 0); load_B(sbase, 0); CP_COMMIT();
    load_A(sbase + STAGE_BYTES, 1); load_B(sbase + STAGE_BYTES, 1); CP_COMMIT();

    #pragma unroll 1
    for (int kt = 0; kt < NKT; kt++) {
        const int s = kt % STAGES;
        CP_WAIT1();                         // stage kt landed (kt+1 in flight)
        __syncthreads();
        const bool pf = (kt + 2 < NKT);
        const int ns = (kt + 2) % STAGES;
        const uint32_t nsb = sbase + ns * STAGE_BYTES;

        const char* ap = smem + s * STAGE_BYTES + (size_t)(wm * 16) * 512 + lane * 16;
        const char* bp = smem + s * STAGE_BYTES + 16384 + (size_t)(wn * 16) * 512 + lane * 16;

        uint4 af[2][4], bf[2][4];
        #pragma unroll
        for (int mt = 0; mt < 4; mt++) af[0][mt] = *(const uint4*)(ap + (mt * 4) * 512);
        #pragma unroll
        for (int j = 0; j < 4; j++)    bf[0][j]  = *(const uint4*)(bp + (j * 4) * 512);

        #pragma unroll
        for (int ks = 0; ks < 4; ks++) {
            const int cur = ks & 1, nxt = cur ^ 1;
            if (ks < 3) {                   // prefetch next ks fragments
                #pragma unroll
                for (int mt = 0; mt < 4; mt++)
                    af[nxt][mt] = *(const uint4*)(ap + (mt * 4 + ks + 1) * 512);
                #pragma unroll
                for (int j = 0; j < 4; j++)
                    bf[nxt][j]  = *(const uint4*)(bp + (j * 4 + ks + 1) * 512);
            }
            if (ks == 0 && pf) load_A(nsb, kt + 2);        // hide LDGSTS issue
            if (ks == 1) { if (pf) load_B(nsb, kt + 2); CP_COMMIT(); }

            #pragma unroll
            for (int mt = 0; mt < 4; mt++)
                #pragma unroll
                for (int j = 0; j < 4; j++) {
                    mma_tf32(c[mt][2 * j],     af[cur][mt].x, af[cur][mt].y,
                             af[cur][mt].z, af[cur][mt].w, bf[cur][j].x, bf[cur][j].y);
                    mma_tf32(c[mt][2 * j + 1], af[cur][mt].x, af[cur][mt].y,
                             af[cur][mt].z, af[cur][mt].w, bf[cur][j].z, bf[cur][j].w);
                }
        }
    }

    // ---- epilogue: shuffle-packed float4 streaming stores, 30 replicas, no smem ----
    const int bm0 = blockIdx.y * BM;
    const int bn0 = blockIdx.x * BN;
    const int odd = lane & 1;
    #pragma unroll
    for (int mt = 0; mt < 4; mt++) {
        const int row = bm0 + wm * 64 + mt * 16 + (lane >> 2) + (odd << 3);
        #pragma unroll
        for (int nt = 0; nt < 8; nt++) {
            const int col = bn0 + wn * 64 + nt * 8 + (lane & 2) * 2;
            const float rx = __shfl_xor_sync(0xffffffffu, c[mt][nt][0], 1);
            const float ry = __shfl_xor_sync(0xffffffffu, c[mt][nt][1], 1);
            const float rz = __shfl_xor_sync(0xffffffffu, c[mt][nt][2], 1);
            const float rw = __shfl_xor_sync(0xffffffffu, c[mt][nt][3], 1);
            float4 v;
            v.x = odd ? rz : c[mt][nt][0];
            v.y = odd ? rw : c[mt][nt][1];
            v.z = odd ? c[mt][nt][2] : rx;
            v.w = odd ? c[mt][nt][3] : ry;
            float* p = out + (size_t)row * OUTN + col;
            #pragma unroll
            for (int rep = 0; rep < NREP; rep++) {
                __stcs((float4*)(p + (size_t)rep * NDIM), v);
            }
        }
    }
}

extern "C" void kernel_launch(void* const* d_in, const int* in_sizes, int n_in,
                              void* d_out, int out_size) {
    const float* x1 = (const float*)d_in[0];
    const float* x2 = (const float*)d_in[1];
    float* out = (float*)d_out;

    prep_kernel<<<3072, 256>>>(x1, x2);

    cudaFuncSetAttribute(Model_82454782148931_gemm,
                         cudaFuncAttributeMaxDynamicSharedMemorySize, SMEM_TOTAL);
    dim3 grid(NDIM / BN, MDIM / BM);   // (32, 16), n fastest (R3 order)
    Model_82454782148931_gemm<<<grid, 128, SMEM_TOTAL>>>(out);
}

// round 8
// speedup vs baseline: 1.4281x; 1.1649x over previous
#include <cuda_runtime.h>
#include <cstdint>

// out[2048,122880] = tile(x1[2048,4096] @ x2[4096,4096], 30x), fp32, TF32 mma.sync.
// R8: latency attack. CTA tile 128x64 (4 warps of 64x32, accum=64 regs) ->
// 4 CTAs/SM = 16 warps/SM, 4 independent warps/SMSP. BK=16, 4-stage cp.async.
#define MDIM 2048
#define NDIM 4096
#define KDIM 4096
#define NREP 30
#define OUTN (NDIM * NREP)

#define BM 128
#define BN 64
#define BK 16
#define NKT (KDIM / BK)          // 256
#define STAGES 4
#define STAGE_BYTES 12288        // 8KB A frags + 4KB B frags
#define SMEM_TOTAL (STAGES * STAGE_BYTES)   // 48KB -> 4 CTAs/SM

__device__ float g_Af[(size_t)MDIM * KDIM];
__device__ float g_Bf[(size_t)NDIM * KDIM];

__device__ __forceinline__ uint32_t f2tf32(float x) {
    uint32_t y;
    asm("cvt.rna.tf32.f32 %0, %1;" : "=r"(y) : "f"(x));
    return y;
}
__device__ __forceinline__ float rtf(float x) { return __uint_as_float(f2tf32(x)); }

__device__ __forceinline__ uint32_t smem_u32(const void* p) {
    uint32_t a;
    asm("{ .reg .u64 t; cvta.to.shared.u64 t, %1; cvt.u32.u64 %0, t; }" : "=r"(a) : "l"(p));
    return a;
}
__device__ __forceinline__ void cp_async16(uint32_t dst, const void* src) {
    asm volatile("cp.async.cg.shared.global [%0], [%1], 16;" :: "r"(dst), "l"(src) : "memory");
}
#define CP_COMMIT() asm volatile("cp.async.commit_group;" ::: "memory")
#define CP_WAIT2()  asm volatile("cp.async.wait_group 2;" ::: "memory")

__device__ __forceinline__ void mma_tf32(float c[4], uint32_t a0, uint32_t a1,
                                         uint32_t a2, uint32_t a3,
                                         uint32_t b0, uint32_t b1) {
    asm volatile(
        "mma.sync.aligned.m16n8k8.row.col.f32.tf32.tf32.f32 "
        "{%0,%1,%2,%3},{%4,%5,%6,%7},{%8,%9},{%0,%1,%2,%3};"
        : "+f"(c[0]), "+f"(c[1]), "+f"(c[2]), "+f"(c[3])
        : "r"(a0), "r"(a1), "r"(a2), "r"(a3), "r"(b0), "r"(b1));
}

// ---------------- fused prepass: blocks [0,1024) do A, [1024,3072) do B ----------------
__global__ __launch_bounds__(256)
void prep_kernel(const float* __restrict__ A, const float* __restrict__ B) {
    __shared__ float sbuf[128 * 68];       // A view 16x516, B view 128x68
    const int tid = threadIdx.x, lane = tid & 31, warp = tid >> 5;
    const int r = lane >> 2, cq = lane & 3;

    if (blockIdx.x < 1024) {
        const int bx = blockIdx.x & 7;      // K/512
        const int m16 = blockIdx.x >> 3;    // M/16
        #pragma unroll
        for (int i = 0; i < 8; i++) {
            const int idx = i * 256 + tid;
            const int rr = idx >> 7, c4 = idx & 127;
            float4 v = *(const float4*)&A[(size_t)(m16 * 16 + rr) * KDIM + bx * 512 + c4 * 4];
            v.x = rtf(v.x); v.y = rtf(v.y); v.z = rtf(v.z); v.w = rtf(v.w);
            *(float4*)&sbuf[rr * 516 + c4 * 4] = v;
        }
        __syncthreads();
        #pragma unroll
        for (int t = 0; t < 8; t++) {
            const int k8l = warp * 8 + t;
            float4 w;
            w.x = sbuf[r * 516 + k8l * 8 + cq];
            w.y = sbuf[(r + 8) * 516 + k8l * 8 + cq];
            w.z = sbuf[r * 516 + k8l * 8 + cq + 4];
            w.w = sbuf[(r + 8) * 516 + k8l * 8 + cq + 4];
            const size_t o = ((size_t)m16 * 512 + bx * 64 + k8l) * 32 + lane;
            ((float4*)g_Af)[o] = w;
        }
    } else {
        const int id = blockIdx.x - 1024;
        const int bx = id & 31;             // K/128
        const int by = id >> 5;             // N/64
        #pragma unroll
        for (int i = 0; i < 8; i++) {
            const int idx = i * 256 + tid;
            const int kr = idx >> 4, c4 = idx & 15;
            float4 v = *(const float4*)&B[(size_t)(bx * 128 + kr) * NDIM + by * 64 + c4 * 4];
            v.x = rtf(v.x); v.y = rtf(v.y); v.z = rtf(v.z); v.w = rtf(v.w);
            *(float4*)&sbuf[kr * 68 + c4 * 4] = v;
        }
        __syncthreads();
        #pragma unroll
        for (int t = 0; t < 8; t++) {
            const int id2 = warp * 8 + t;
            const int n16l = id2 >> 4, k8l = id2 & 15;
            float4 w;
            w.x = sbuf[(k8l * 8 + cq) * 68 + n16l * 16 + r];
            w.y = sbuf[(k8l * 8 + cq + 4) * 68 + n16l * 16 + r];
            w.z = sbuf[(k8l * 8 + cq) * 68 + n16l * 16 + 8 + r];
            w.w = sbuf[(k8l * 8 + cq + 4) * 68 + n16l * 16 + 8 + r];
            const size_t o = ((size_t)(by * 4 + n16l) * 512 + bx * 16 + k8l) * 32 + lane;
            ((float4*)g_Bf)[o] = w;
        }
    }
}

// ---------------- GEMM: 128x64x16, 4 warps of 64x32, 4 CTAs/SM, 4-stage ----------------
__global__ __launch_bounds__(128, 4)
void Model_82454782148931_gemm(float* __restrict__ out) {
    extern __shared__ char smem[];
    const uint32_t sbase = smem_u32(smem);
    const int tid  = threadIdx.x;
    const int lane = tid & 31;
    const int warp = tid >> 5;
    const int wm   = warp >> 1;             // 0..1 -> 64-row slab
    const int wn   = warp & 1;              // 0..1 -> 32-col slab
    const int ni   = blockIdx.x;            // 0..63 (n fastest: wave shares slabs in L2)
    const int mi   = blockIdx.y;            // 0..15
    const int bm16 = mi * 8;
    const int bn16 = ni * 4;

    const float4* Af4 = (const float4*)g_Af;
    const float4* Bf4 = (const float4*)g_Bf;

    float c[4][4][4];
    #pragma unroll
    for (int mt = 0; mt < 4; mt++)
        #pragma unroll
        for (int nt = 0; nt < 4; nt++)
            #pragma unroll
            for (int i = 0; i < 4; i++) c[mt][nt][i] = 0.0f;

    // stage: A frags (m16l*2+k8l)*512 at 0 (8KB); B frags (n16l*2+k8l)*512 at 8192 (4KB)
    auto load_stage = [&](int s, int kt) {
        const uint32_t ab = sbase + s * STAGE_BYTES;
        #pragma unroll
        for (int i = 0; i < 4; i++) {       // A: 512 float4
            const int idx = i * 128 + tid;
            const int m16l = idx >> 6;
            const int k8l  = (idx >> 5) & 1;
            const int ln   = idx & 31;
            cp_async16(ab + idx * 16,
                       Af4 + ((size_t)(bm16 + m16l) * 512 + kt * 2 + k8l) * 32 + ln);
        }
        #pragma unroll
        for (int i = 0; i < 2; i++) {       // B: 256 float4
            const int idx = i * 128 + tid;
            const int n16l = idx >> 6;
            const int k8l  = (idx >> 5) & 1;
            const int ln   = idx & 31;
            cp_async16(ab + 8192 + idx * 16,
                       Bf4 + ((size_t)(bn16 + n16l) * 512 + kt * 2 + k8l) * 32 + ln);
        }
    };

    load_stage(0, 0); CP_COMMIT();
    load_stage(1, 1); CP_COMMIT();
    load_stage(2, 2); CP_COMMIT();

    #pragma unroll 1
    for (int kt = 0; kt < NKT; kt++) {
        const int s = kt & 3;
        CP_WAIT2();                         // stage kt landed (kt+1, kt+2 in flight)
        __syncthreads();
        if (kt + 3 < NKT) load_stage((kt + 3) & 3, kt + 3);
        CP_COMMIT();

        const char* ap = smem + s * STAGE_BYTES + (size_t)(wm * 4) * 2 * 512 + lane * 16;
        const char* bp = smem + s * STAGE_BYTES + 8192 + (size_t)(wn * 2) * 2 * 512 + lane * 16;
        #pragma unroll
        for (int ks = 0; ks < 2; ks++) {
            uint4 af[4], bf[2];
            #pragma unroll
            for (int mt = 0; mt < 4; mt++)
                af[mt] = *(const uint4*)(ap + (mt * 2 + ks) * 512);
            #pragma unroll
            for (int j = 0; j < 2; j++)
                bf[j]  = *(const uint4*)(bp + (j * 2 + ks) * 512);
            #pragma unroll
            for (int mt = 0; mt < 4; mt++)
                #pragma unroll
                for (int j = 0; j < 2; j++) {
                    mma_tf32(c[mt][2 * j],     af[mt].x, af[mt].y, af[mt].z, af[mt].w,
                             bf[j].x, bf[j].y);
                    mma_tf32(c[mt][2 * j + 1], af[mt].x, af[mt].y, af[mt].z, af[mt].w,
                             bf[j].z, bf[j].w);
                }
        }
    }

    // ---- epilogue: 30 replicas straight from registers, full-sector float2 __stcs ----
    const int bm0 = mi * BM;
    const int bn0 = ni * BN;
    #pragma unroll
    for (int mt = 0; mt < 4; mt++) {
        const int row0 = bm0 + wm * 64 + mt * 16 + (lane >> 2);
        #pragma unroll
        for (int nt = 0; nt < 4; nt++) {
            const int col = bn0 + wn * 32 + nt * 8 + (lane & 3) * 2;
            const float2 v01 = make_float2(c[mt][nt][0], c[mt][nt][1]);
            const float2 v23 = make_float2(c[mt][nt][2], c[mt][nt][3]);
            float* p0 = out + (size_t)row0 * OUTN + col;
            float* p1 = p0 + (size_t)8 * OUTN;
            #pragma unroll
            for (int rep = 0; rep < NREP; rep++) {
                __stcs((float2*)(p0 + (size_t)rep * NDIM), v01);
                __stcs((float2*)(p1 + (size_t)rep * NDIM), v23);
            }
        }
    }
}

extern "C" void kernel_launch(void* const* d_in, const int* in_sizes, int n_in,
                              void* d_out, int out_size) {
    const float* x1 = (const float*)d_in[0];
    const float* x2 = (const float*)d_in[1];
    float* out = (float*)d_out;

    prep_kernel<<<3072, 256>>>(x1, x2);

    cudaFuncSetAttribute(Model_82454782148931_gemm,
                         cudaFuncAttributeMaxDynamicSharedMemorySize, SMEM_TOTAL);
    dim3 grid(NDIM / BN, MDIM / BM);   // (64, 16), n fastest
    Model_82454782148931_gemm<<<grid, 128, SMEM_TOTAL>>>(out);
}